// round 15
// baseline (speedup 1.0000x reference)
#include <cuda_runtime.h>
#include <cuda_fp16.h>
#include <cstdint>

// BiaffineAttention  B=16, S=512, H=1024, A=500 (padded to 512)
// GEMMs via mma.sync fp16 (m16n8k16), fp32 accum, 3-stage cp.async pipeline.
// Weights pre-scaled by 32, descaled in epilogue (fp16-lo limbs stay normal).
//   TT   = ReLU(X @ [w1h;w1d]^T + b1c)   1-pass -> fp16 hi
//   W'   = Wb @ w2d (3-pass, hi store) ; b' = Wb @ b2d
//   head = TT[:, :512] @ w2h^T + b2h     1-pass -> fp16 hi   (z=0)
//   depW = TT[:, 512:] @ W'^T + b'       1-pass -> fp16 hi   (z=1)
//   out[b] = head[b] @ depW[b]^T + bb    1-pass (fp32 out)
// R15: warp kh-skew + ldsm/MMA interleave to break post-barrier lockstep.

// ============================ PTX helpers ============================
__device__ __forceinline__ uint32_t smem_u32(const void* p) {
    uint32_t a;
    asm("{ .reg .u64 t; cvta.to.shared.u64 t, %1; cvt.u32.u64 %0, t; }"
        : "=r"(a) : "l"(p));
    return a;
}

__device__ __forceinline__ void ldsm4(uint32_t* r, uint32_t addr) {
    asm volatile("ldmatrix.sync.aligned.m8n8.x4.shared.b16 {%0,%1,%2,%3}, [%4];"
        : "=r"(r[0]), "=r"(r[1]), "=r"(r[2]), "=r"(r[3]) : "r"(addr));
}

__device__ __forceinline__ void mma_f16(float* c, const uint32_t* a,
                                        uint32_t b0, uint32_t b1) {
    asm volatile("mma.sync.aligned.m16n8k16.row.col.f32.f16.f16.f32 "
        "{%0,%1,%2,%3}, {%4,%5,%6,%7}, {%8,%9}, {%0,%1,%2,%3};"
        : "+f"(c[0]), "+f"(c[1]), "+f"(c[2]), "+f"(c[3])
        : "r"(a[0]), "r"(a[1]), "r"(a[2]), "r"(a[3]), "r"(b0), "r"(b1));
}

#define CP16(s, g) \
    asm volatile("cp.async.cg.shared.global [%0], [%1], 16;" :: "r"(s), "l"(g))
#define CP_COMMIT() asm volatile("cp.async.commit_group;" ::: "memory")
#define CP_WAIT0()  asm volatile("cp.async.wait_group 0;" ::: "memory")
#define CP_WAIT1()  asm volatile("cp.async.wait_group 1;" ::: "memory")

// ============================ scratch ============================
static constexpr long long EL_X   = 8192LL * 1024;
static constexpr long long EL_W1C = 1024LL * 1024;
static constexpr long long EL_S   = 512LL * 512;
static constexpr long long EL_TT  = 8192LL * 1024;
static constexpr long long EL_ACT = 8192LL * 512;

static constexpr long long O_XH     = 0;
static constexpr long long O_W1C_H  = O_XH + EL_X;
static constexpr long long O_W2H_H  = O_W1C_H + EL_W1C;
static constexpr long long O_WB_H   = O_W2H_H + EL_S;
static constexpr long long O_WB_L   = O_WB_H + EL_S;
static constexpr long long O_W2DT_H = O_WB_L + EL_S;
static constexpr long long O_W2DT_L = O_W2DT_H + EL_S;
static constexpr long long O_WP_H   = O_W2DT_L + EL_S;
static constexpr long long O_TT_H   = O_WP_H + EL_S;
static constexpr long long O_HD_H   = O_TT_H + EL_TT;
static constexpr long long O_DW_H   = O_HD_H + EL_ACT;
static constexpr long long H_TOTAL  = O_DW_H + EL_ACT;

__device__ __align__(1024) __half g_h[H_TOTAL];
__device__ __align__(1024) float g_vec[3 * 1024];   // b1c[1024], b2h_p[512], bpr[512]

// ============================ prep kernels ============================
__device__ __forceinline__ void split_h(__half* hi, __half* lo, long long i, float v)
{
    __half h = __float2half_rn(v);
    hi[i] = h;
    lo[i] = __float2half_rn(v - __half2float(h));
}

__global__ void conv_x(const float* __restrict__ X, __half* __restrict__ Xh)
{
    long long idx = ((long long)blockIdx.x * blockDim.x + threadIdx.x) * 4;
    float4 v = *(const float4*)(X + idx);
    __half h[4] = {__float2half_rn(v.x), __float2half_rn(v.y),
                   __float2half_rn(v.z), __float2half_rn(v.w)};
    *(uint2*)(Xh + idx) = *(uint2*)h;
}

#define WSCALE 32.0f
#define CDESC  0.03125f

__global__ void prep_weights(
    const float* __restrict__ w1h, const float* __restrict__ w1d,
    const float* __restrict__ w2h, const float* __restrict__ Wb,
    const float* __restrict__ w2d,
    const float* __restrict__ b1h, const float* __restrict__ b1d,
    const float* __restrict__ b2h, const float* __restrict__ b2d,
    __half* __restrict__ W1Ch,
    __half* __restrict__ W2Hh,
    __half* __restrict__ WBh,  __half* __restrict__ WBl,
    __half* __restrict__ W2DTh,__half* __restrict__ W2DTl,
    float* __restrict__ b1c, float* __restrict__ b2h_p, float* __restrict__ bpr)
{
    const int bx = blockIdx.x;
    const int tid = threadIdx.x;

    if (bx < 4096) {
        const int half_ = bx >> 11;
        const long long e = ((long long)(bx & 2047)) * 256 + tid;
        const int r = (int)(e >> 10);
        const float* src = half_ ? w1d : w1h;
        float v = (r < 500) ? WSCALE * src[(long long)r * 1024 + (e & 1023)] : 0.0f;
        W1Ch[(long long)half_ * 512 * 1024 + e] = __float2half_rn(v);
    } else if (bx < 7168) {
        const int sec = (bx - 4096) >> 10;
        const long long e = ((long long)((bx - 4096) & 1023)) * 256 + tid;
        const int r = (int)(e >> 9), c = (int)(e & 511);
        float v = 0.0f;
        if (sec == 0) {
            if (r < 500 && c < 500) v = WSCALE * w2h[r * 500 + c];
            W2Hh[e] = __float2half_rn(v);
        } else if (sec == 1) {
            if (r < 500 && c < 500) v = WSCALE * Wb[r * 500 + c];
            split_h(WBh, WBl, e, v);
        } else {
            if (r < 500 && c < 500) v = WSCALE * w2d[c * 500 + r];
            split_h(W2DTh, W2DTl, e, v);
        }
    } else if (bx < 7680) {
        const int j = bx - 7168;
        __shared__ float red[8];
        float s = 0.0f;
        if (j < 500)
            for (int a = tid; a < 500; a += 256) s += Wb[j * 500 + a] * b2d[a];
#pragma unroll
        for (int o = 16; o > 0; o >>= 1) s += __shfl_down_sync(0xffffffffu, s, o);
        if ((tid & 31) == 0) red[tid >> 5] = s;
        __syncthreads();
        if (tid == 0) {
            float t = 0.0f;
#pragma unroll
            for (int q = 0; q < 8; q++) t += red[q];
            bpr[j] = (j < 500) ? t : 0.0f;
        }
    } else {
        const int e = (bx - 7680) * 256 + tid;
        if (e < 1024) {
            const int c = e & 511;
            b1c[e] = (c < 500) ? ((e < 512) ? b1h[c] : b1d[c]) : 0.0f;
        } else if (e < 1536) {
            const int c = e - 1024;
            b2h_p[c] = (c < 500) ? b2h[c] : 0.0f;
        }
    }
}

// ============================ main GEMM ============================
// C[M,N] = A[M,K] @ B[N,K]^T.
// PASSES=1: Ahi@Bhi.  PASSES=3: + Ahi@Blo + Alo@Bhi.
// CTA 128x128, 8 warps (4Mx2N), warp 32x64, BK=32, 3-stage cp.async ring,
// ONE __syncthreads per k-iter. Warp kh-skew + ldsm/MMA interleave.
// splitOut: 0=fp32, 2=fp16 hi only. dual: z picks operand set.
#define SROW 40
#define TILEB (128 * SROW * 2)   // 10240 B per matrix tile

template<int PASSES>
struct Lay {
    static constexpr int NT = (PASSES == 1) ? 2 : (PASSES == 2) ? 3 : 4;
    static constexpr int STAGEB = NT * TILEB;
    static constexpr int AH = 0;
    static constexpr int AL = (PASSES == 3) ? TILEB : 0;
    static constexpr int BH = (PASSES == 3) ? 2 * TILEB : TILEB;
    static constexpr int BL = (PASSES == 2) ? 2 * TILEB : 3 * TILEB;
    static constexpr int SMEM = 3 * STAGEB;
};

template<int PASSES>
__device__ __forceinline__ void issue_tile(
    uint32_t sbase, const char* Ah, const char* Al, const char* Bh, const char* Bl,
    int lda, int ldb, int row0, int col0, int k0, int tid)
{
    using L = Lay<PASSES>;
#pragma unroll
    for (int i = 0; i < 2; i++) {
        const int pos = tid + i * 256;
        const int r = pos >> 2, ch = pos & 3;
        const uint32_t so = (uint32_t)(r * (SROW * 2) + ch * 16);
        const size_t gA = ((size_t)(row0 + r) * lda + k0 + ch * 8) * 2;
        const size_t gB = ((size_t)(col0 + r) * ldb + k0 + ch * 8) * 2;
        CP16(sbase + L::AH + so, Ah + gA);
        if (PASSES == 3) CP16(sbase + L::AL + so, Al + gA);
        CP16(sbase + L::BH + so, Bh + gB);
        if (PASSES >= 2) CP16(sbase + L::BL + so, Bl + gB);
    }
}

template<int PASSES>
__global__ void __launch_bounds__(256, 2) gemm_mma(
    const __half* __restrict__ Ahi, const __half* __restrict__ Alo,
    int lda, long long sA,
    const __half* __restrict__ Bhi, const __half* __restrict__ Blo,
    const __half* __restrict__ Bhi2, int ldb, long long sB,
    void* __restrict__ Cout, void* __restrict__ CoutB,
    int ldc, long long sC,
    int K, const float* __restrict__ bias, const float* __restrict__ bias2,
    int biasMode, float cScale, int doRelu, int splitOut, int dual)
{
    using L = Lay<PASSES>;
    extern __shared__ char smem[];
    const uint32_t sb = smem_u32(smem);
    const int tid  = threadIdx.x;
    const int lane = tid & 31;
    const int wid  = tid >> 5;
    const int wm   = wid & 3;
    const int wn   = wid >> 2;
    const int row0 = blockIdx.y * 128;
    const int col0 = blockIdx.x * 128;

    const int z = blockIdx.z;
    const char *Ah, *Al, *Bh, *Bl;
    const float* bvp = bias;
    void *Co = Cout;
    if (dual && z) {
        Ah = (const char*)(Ahi + 512);
        Al = nullptr;
        Bh = (const char*)Bhi2;  Bl = nullptr;
        bvp = bias2;  Co = CoutB;
    } else {
        Ah = (const char*)(Ahi + (long long)z * sA);
        Al = (const char*)(Alo ? Alo + (long long)z * sA : nullptr);
        Bh = (const char*)(Bhi + (long long)z * sB);
        Bl = (const char*)(Blo ? Blo + (long long)z * sB : nullptr);
    }

    float acc[2][8][4];
#pragma unroll
    for (int mt = 0; mt < 2; mt++)
#pragma unroll
        for (int nt = 0; nt < 8; nt++)
#pragma unroll
            for (int q = 0; q < 4; q++) acc[mt][nt][q] = 0.0f;

    const int frow = (lane & 7) | (((lane >> 3) & 1) << 3);
    const int fkc  = (lane >> 4) * 8;
    const int khFirst = wid & 1;          // warp kh-skew

    const int T = K / 32;   // >= 16 always
    issue_tile<PASSES>(sb + 0 * L::STAGEB, Ah, Al, Bh, Bl, lda, ldb, row0, col0, 0, tid);
    CP_COMMIT();
    issue_tile<PASSES>(sb + 1 * L::STAGEB, Ah, Al, Bh, Bl, lda, ldb, row0, col0, 32, tid);
    CP_COMMIT();

    int sidx = 0;
    for (int t = 0; t < T; ++t) {
        if (t + 1 < T) { CP_WAIT1(); } else { CP_WAIT0(); }
        __syncthreads();

        const uint32_t st = sb + sidx * L::STAGEB;
#pragma unroll
        for (int kk = 0; kk < 2; ++kk) {
            const int kh = kk ^ khFirst;   // half the warps run (1,0), half (0,1)
            const int kb = kh * 16 + fkc;
            if (PASSES == 1) {
                // interleaved ldsm/MMA: each B fragment gets MMA shadow
                uint32_t ah[2][4], bh4[4][4];
                ldsm4(ah[0], st + L::AH +
                      (uint32_t)(((wm * 32 + 0 * 16 + frow) * SROW + kb) * 2));
                ldsm4(ah[1], st + L::AH +
                      (uint32_t)(((wm * 32 + 1 * 16 + frow) * SROW + kb) * 2));
                ldsm4(bh4[0], st + L::BH +
                      (uint32_t)(((wn * 64 + 0 * 16 + frow) * SROW + kb) * 2));
                ldsm4(bh4[1], st + L::BH +
                      (uint32_t)(((wn * 64 + 1 * 16 + frow) * SROW + kb) * 2));
#pragma unroll
                for (int p = 0; p < 2; p++)
#pragma unroll
                    for (int mt = 0; mt < 2; mt++)
                        mma_f16(acc[mt][0 * 2 + p], ah[mt], bh4[0][p], bh4[0][p + 2]);
                ldsm4(bh4[2], st + L::BH +
                      (uint32_t)(((wn * 64 + 2 * 16 + frow) * SROW + kb) * 2));
#pragma unroll
                for (int p = 0; p < 2; p++)
#pragma unroll
                    for (int mt = 0; mt < 2; mt++)
                        mma_f16(acc[mt][1 * 2 + p], ah[mt], bh4[1][p], bh4[1][p + 2]);
                ldsm4(bh4[3], st + L::BH +
                      (uint32_t)(((wn * 64 + 3 * 16 + frow) * SROW + kb) * 2));
#pragma unroll
                for (int p = 0; p < 2; p++)
#pragma unroll
                    for (int mt = 0; mt < 2; mt++)
                        mma_f16(acc[mt][2 * 2 + p], ah[mt], bh4[2][p], bh4[2][p + 2]);
#pragma unroll
                for (int p = 0; p < 2; p++)
#pragma unroll
                    for (int mt = 0; mt < 2; mt++)
                        mma_f16(acc[mt][3 * 2 + p], ah[mt], bh4[3][p], bh4[3][p + 2]);
            } else {
                uint32_t ah[2][4], al[2][4];
#pragma unroll
                for (int mt = 0; mt < 2; mt++) {
                    const uint32_t off =
                        (uint32_t)(((wm * 32 + mt * 16 + frow) * SROW + kb) * 2);
                    ldsm4(ah[mt], st + L::AH + off);
                    if (PASSES == 3) ldsm4(al[mt], st + L::AL + off);
                }
#pragma unroll
                for (int bt = 0; bt < 4; bt++) {
                    uint32_t bh[4], bl[4];
                    const uint32_t off =
                        (uint32_t)(((wn * 64 + bt * 16 + frow) * SROW + kb) * 2);
                    ldsm4(bh, st + L::BH + off);
                    ldsm4(bl, st + L::BL + off);
#pragma unroll
                    for (int mt = 0; mt < 2; mt++)
#pragma unroll
                        for (int p = 0; p < 2; p++)
                            mma_f16(acc[mt][bt * 2 + p], ah[mt], bh[p], bh[p + 2]);
#pragma unroll
                    for (int mt = 0; mt < 2; mt++)
#pragma unroll
                        for (int p = 0; p < 2; p++)
                            mma_f16(acc[mt][bt * 2 + p], ah[mt], bl[p], bl[p + 2]);
                    if (PASSES == 3) {
#pragma unroll
                        for (int mt = 0; mt < 2; mt++)
#pragma unroll
                            for (int p = 0; p < 2; p++)
                                mma_f16(acc[mt][bt * 2 + p], al[mt], bh[p], bh[p + 2]);
                    }
                }
            }
        }

        if (t + 2 < T) {
            int widx = sidx + 2; if (widx >= 3) widx -= 3;
            issue_tile<PASSES>(sb + widx * L::STAGEB, Ah, Al, Bh, Bl,
                               lda, ldb, row0, col0, (t + 2) * 32, tid);
            CP_COMMIT();
        }
        sidx = (sidx + 1 == 3) ? 0 : sidx + 1;
    }

    // ============================ epilogue ============================
    const int cbytes = (splitOut == 0) ? 4 : 2;
    char* Cb = (char*)Co + (dual ? 0 : (size_t)z * sC * cbytes);

#pragma unroll
    for (int mt = 0; mt < 2; mt++) {
        const long long r0 = row0 + wm * 32 + mt * 16 + (lane >> 2);
#pragma unroll
        for (int nt = 0; nt < 8; nt++) {
            const int c0 = col0 + wn * 64 + nt * 8 + (lane & 3) * 2;
            float b0 = 0.0f, b1 = 0.0f;
            if (biasMode == 1)      { b0 = bvp[c0]; b1 = bvp[c0 + 1]; }
            else if (biasMode == 2) { b0 = bvp[0];  b1 = bvp[0]; }

            float v00 = fmaf(acc[mt][nt][0], cScale, b0);
            float v01 = fmaf(acc[mt][nt][1], cScale, b1);
            float v10 = fmaf(acc[mt][nt][2], cScale, b0);
            float v11 = fmaf(acc[mt][nt][3], cScale, b1);
            if (doRelu) {
                v00 = fmaxf(v00, 0.0f); v01 = fmaxf(v01, 0.0f);
                v10 = fmaxf(v10, 0.0f); v11 = fmaxf(v11, 0.0f);
            }

            if (splitOut == 0) {
                *(float2*)(Cb + (r0 * ldc + c0) * 4)       = make_float2(v00, v01);
                *(float2*)(Cb + ((r0 + 8) * ldc + c0) * 4) = make_float2(v10, v11);
            } else {
                __half h00 = __float2half_rn(v00), h01 = __float2half_rn(v01);
                __half h10 = __float2half_rn(v10), h11 = __float2half_rn(v11);
                uint32_t ph0 = (uint32_t)__half_as_ushort(h00) |
                               ((uint32_t)__half_as_ushort(h01) << 16);
                uint32_t ph1 = (uint32_t)__half_as_ushort(h10) |
                               ((uint32_t)__half_as_ushort(h11) << 16);
                *(uint32_t*)(Cb + (r0 * ldc + c0) * 2)       = ph0;
                *(uint32_t*)(Cb + ((r0 + 8) * ldc + c0) * 2) = ph1;
            }
        }
    }
}

// ============================ launch ============================
extern "C" void kernel_launch(void* const* d_in, const int* in_sizes, int n_in,
                              void* d_out, int out_size)
{
    const float* X   = (const float*)d_in[0];
    const float* w1h = (const float*)d_in[1];
    const float* b1h = (const float*)d_in[2];
    const float* w2h = (const float*)d_in[3];
    const float* b2h = (const float*)d_in[4];
    const float* w1d = (const float*)d_in[5];
    const float* b1d = (const float*)d_in[6];
    const float* w2d = (const float*)d_in[7];
    const float* b2d = (const float*)d_in[8];
    const float* Wb  = (const float*)d_in[9];
    const float* bb  = (const float*)d_in[10];
    float* out = (float*)d_out;

    __half* hb = nullptr;
    cudaGetSymbolAddress((void**)&hb, g_h);
    float* vecs = nullptr;
    cudaGetSymbolAddress((void**)&vecs, g_vec);

    __half *Xh    = hb + O_XH;
    __half *W1Ch  = hb + O_W1C_H;
    __half *W2Hh  = hb + O_W2H_H;
    __half *WBh   = hb + O_WB_H,   *WBl   = hb + O_WB_L;
    __half *W2DTh = hb + O_W2DT_H, *W2DTl = hb + O_W2DT_L;
    __half *WPh   = hb + O_WP_H;
    __half *TTh   = hb + O_TT_H;
    __half *HDh   = hb + O_HD_H;
    __half *DWh   = hb + O_DW_H;

    float* b1c   = vecs + 0 * 1024;
    float* b2h_p = vecs + 1 * 1024;
    float* bpr   = vecs + 2 * 1024;

    cudaFuncSetAttribute(gemm_mma<1>, cudaFuncAttributeMaxDynamicSharedMemorySize,
                         Lay<1>::SMEM);
    cudaFuncSetAttribute(gemm_mma<3>, cudaFuncAttributeMaxDynamicSharedMemorySize,
                         Lay<3>::SMEM);

    // launch 0: X -> fp16
    conv_x<<<(unsigned)(EL_X / 4 / 256), 256>>>(X, Xh);
    // launch 1: weight prep (scaled x32) + biases
    prep_weights<<<7686, 256>>>(w1h, w1d, w2h, Wb, w2d, b1h, b1d, b2h, b2d,
                                W1Ch, W2Hh, WBh, WBl, W2DTh, W2DTl,
                                b1c, b2h_p, bpr);

    // launch 2: W' = Wb @ w2d (3-pass, hi-only store of 32*W')
    {
        dim3 g(4, 4, 1);
        gemm_mma<3><<<g, 256, Lay<3>::SMEM>>>(
            WBh, WBl, 512, 0, W2DTh, W2DTl, nullptr, 512, 0,
            WPh, nullptr, 512, 0, 512, nullptr, nullptr, 0, CDESC, 0, 2, 0);
    }
    // launch 3: stage 1: TT = ReLU(X @ W1C^T /32 + b1c), 1-pass, hi out
    {
        dim3 g(8, 64, 1);
        gemm_mma<1><<<g, 256, Lay<1>::SMEM>>>(
            Xh, nullptr, 1024, 0, W1Ch, nullptr, nullptr, 1024, 0,
            TTh, nullptr, 1024, 0, 1024, b1c, nullptr, 1, CDESC, 1, 2, 0);
    }
    // launch 4: stage 2 merged, 1-pass (z=0: head -> hi; z=1: depW -> hi)
    {
        dim3 g(4, 64, 2);
        gemm_mma<1><<<g, 256, Lay<1>::SMEM>>>(
            TTh, nullptr, 1024, 0, W2Hh, nullptr, WPh, 512, 0,
            HDh, DWh, 512, 0, 512, b2h_p, bpr, 1, CDESC, 0, 2, 1);
    }
    // launch 5: final batched, 1-pass: out[b] = head[b] @ depW[b]^T + bb (fp32)
    {
        dim3 g(4, 4, 16);
        const long long sAB = 512LL * 512;
        gemm_mma<1><<<g, 256, Lay<1>::SMEM>>>(
            HDh, nullptr, 512, sAB, DWh, nullptr, nullptr, 512, sAB,
            out, nullptr, 512, sAB, 512, bb, nullptr, 2, 1.0f, 0, 0, 0);
    }
}

// round 16
// speedup vs baseline: 1.0551x; 1.0551x over previous
#include <cuda_runtime.h>
#include <cuda_fp16.h>
#include <cstdint>

// BiaffineAttention  B=16, S=512, H=1024, A=500 (padded to 512)
// GEMMs via mma.sync fp16 (m16n8k16), fp32 accum, 3-stage cp.async pipeline.
// Weights pre-scaled by 32, descaled in epilogue.
//   TT   = ReLU(X @ [w1h;w1d]^T + b1c)   1-pass -> fp16 hi
//   W'   = Wb @ w2d (3-pass, hi store) ; b' = Wb @ b2d
//   head = TT[:, :512] @ w2h^T + b2h     1-pass -> fp16 hi   (z=0)
//   depW = TT[:, 512:] @ W'^T + b'       1-pass -> fp16 hi   (z=1)
//   out[b] = head[b] @ depW[b]^T + bb    1-pass (fp32 out)
// R16: 512 threads / 16 warps per CTA (warp tile 32x32), 2 CTAs/SM ->
//      8 warps/SMSP for latency hiding (was 4).

// ============================ PTX helpers ============================
__device__ __forceinline__ uint32_t smem_u32(const void* p) {
    uint32_t a;
    asm("{ .reg .u64 t; cvta.to.shared.u64 t, %1; cvt.u32.u64 %0, t; }"
        : "=r"(a) : "l"(p));
    return a;
}

__device__ __forceinline__ void ldsm4(uint32_t* r, uint32_t addr) {
    asm volatile("ldmatrix.sync.aligned.m8n8.x4.shared.b16 {%0,%1,%2,%3}, [%4];"
        : "=r"(r[0]), "=r"(r[1]), "=r"(r[2]), "=r"(r[3]) : "r"(addr));
}

__device__ __forceinline__ void mma_f16(float* c, const uint32_t* a,
                                        uint32_t b0, uint32_t b1) {
    asm volatile("mma.sync.aligned.m16n8k16.row.col.f32.f16.f16.f32 "
        "{%0,%1,%2,%3}, {%4,%5,%6,%7}, {%8,%9}, {%0,%1,%2,%3};"
        : "+f"(c[0]), "+f"(c[1]), "+f"(c[2]), "+f"(c[3])
        : "r"(a[0]), "r"(a[1]), "r"(a[2]), "r"(a[3]), "r"(b0), "r"(b1));
}

#define CP16(s, g) \
    asm volatile("cp.async.cg.shared.global [%0], [%1], 16;" :: "r"(s), "l"(g))
#define CP_COMMIT() asm volatile("cp.async.commit_group;" ::: "memory")
#define CP_WAIT0()  asm volatile("cp.async.wait_group 0;" ::: "memory")
#define CP_WAIT1()  asm volatile("cp.async.wait_group 1;" ::: "memory")

// ============================ scratch ============================
static constexpr long long EL_X   = 8192LL * 1024;
static constexpr long long EL_W1C = 1024LL * 1024;
static constexpr long long EL_S   = 512LL * 512;
static constexpr long long EL_TT  = 8192LL * 1024;
static constexpr long long EL_ACT = 8192LL * 512;

static constexpr long long O_XH     = 0;
static constexpr long long O_W1C_H  = O_XH + EL_X;
static constexpr long long O_W2H_H  = O_W1C_H + EL_W1C;
static constexpr long long O_WB_H   = O_W2H_H + EL_S;
static constexpr long long O_WB_L   = O_WB_H + EL_S;
static constexpr long long O_W2DT_H = O_WB_L + EL_S;
static constexpr long long O_W2DT_L = O_W2DT_H + EL_S;
static constexpr long long O_WP_H   = O_W2DT_L + EL_S;
static constexpr long long O_TT_H   = O_WP_H + EL_S;
static constexpr long long O_HD_H   = O_TT_H + EL_TT;
static constexpr long long O_DW_H   = O_HD_H + EL_ACT;
static constexpr long long H_TOTAL  = O_DW_H + EL_ACT;

__device__ __align__(1024) __half g_h[H_TOTAL];
__device__ __align__(1024) float g_vec[3 * 1024];   // b1c[1024], b2h_p[512], bpr[512]

// ============================ prep kernels ============================
__device__ __forceinline__ void split_h(__half* hi, __half* lo, long long i, float v)
{
    __half h = __float2half_rn(v);
    hi[i] = h;
    lo[i] = __float2half_rn(v - __half2float(h));
}

__global__ void conv_x(const float* __restrict__ X, __half* __restrict__ Xh)
{
    long long idx = ((long long)blockIdx.x * blockDim.x + threadIdx.x) * 4;
    float4 v = *(const float4*)(X + idx);
    __half h[4] = {__float2half_rn(v.x), __float2half_rn(v.y),
                   __float2half_rn(v.z), __float2half_rn(v.w)};
    *(uint2*)(Xh + idx) = *(uint2*)h;
}

#define WSCALE 32.0f
#define CDESC  0.03125f

__global__ void prep_weights(
    const float* __restrict__ w1h, const float* __restrict__ w1d,
    const float* __restrict__ w2h, const float* __restrict__ Wb,
    const float* __restrict__ w2d,
    const float* __restrict__ b1h, const float* __restrict__ b1d,
    const float* __restrict__ b2h, const float* __restrict__ b2d,
    __half* __restrict__ W1Ch,
    __half* __restrict__ W2Hh,
    __half* __restrict__ WBh,  __half* __restrict__ WBl,
    __half* __restrict__ W2DTh,__half* __restrict__ W2DTl,
    float* __restrict__ b1c, float* __restrict__ b2h_p, float* __restrict__ bpr)
{
    const int bx = blockIdx.x;
    const int tid = threadIdx.x;

    if (bx < 4096) {
        const int half_ = bx >> 11;
        const long long e = ((long long)(bx & 2047)) * 256 + tid;
        const int r = (int)(e >> 10);
        const float* src = half_ ? w1d : w1h;
        float v = (r < 500) ? WSCALE * src[(long long)r * 1024 + (e & 1023)] : 0.0f;
        W1Ch[(long long)half_ * 512 * 1024 + e] = __float2half_rn(v);
    } else if (bx < 7168) {
        const int sec = (bx - 4096) >> 10;
        const long long e = ((long long)((bx - 4096) & 1023)) * 256 + tid;
        const int r = (int)(e >> 9), c = (int)(e & 511);
        float v = 0.0f;
        if (sec == 0) {
            if (r < 500 && c < 500) v = WSCALE * w2h[r * 500 + c];
            W2Hh[e] = __float2half_rn(v);
        } else if (sec == 1) {
            if (r < 500 && c < 500) v = WSCALE * Wb[r * 500 + c];
            split_h(WBh, WBl, e, v);
        } else {
            if (r < 500 && c < 500) v = WSCALE * w2d[c * 500 + r];
            split_h(W2DTh, W2DTl, e, v);
        }
    } else if (bx < 7680) {
        const int j = bx - 7168;
        __shared__ float red[8];
        float s = 0.0f;
        if (j < 500)
            for (int a = tid; a < 500; a += 256) s += Wb[j * 500 + a] * b2d[a];
#pragma unroll
        for (int o = 16; o > 0; o >>= 1) s += __shfl_down_sync(0xffffffffu, s, o);
        if ((tid & 31) == 0) red[tid >> 5] = s;
        __syncthreads();
        if (tid == 0) {
            float t = 0.0f;
#pragma unroll
            for (int q = 0; q < 8; q++) t += red[q];
            bpr[j] = (j < 500) ? t : 0.0f;
        }
    } else {
        const int e = (bx - 7680) * 256 + tid;
        if (e < 1024) {
            const int c = e & 511;
            b1c[e] = (c < 500) ? ((e < 512) ? b1h[c] : b1d[c]) : 0.0f;
        } else if (e < 1536) {
            const int c = e - 1024;
            b2h_p[c] = (c < 500) ? b2h[c] : 0.0f;
        }
    }
}

// ============================ main GEMM ============================
// C[M,N] = A[M,K] @ B[N,K]^T.
// PASSES=1: Ahi@Bhi.  PASSES=3: + Ahi@Blo + Alo@Bhi.
// CTA 128x128, 512 threads = 16 warps (4M x 4N), warp tile 32x32, BK=32,
// 3-stage cp.async ring, one __syncthreads per k-iter, 2 CTAs/SM.
// splitOut: 0=fp32, 2=fp16 hi only. dual: z picks operand set.
#define SROW 40
#define TILEB (128 * SROW * 2)   // 10240 B per matrix tile

template<int PASSES>
struct Lay {
    static constexpr int NT = (PASSES == 1) ? 2 : (PASSES == 2) ? 3 : 4;
    static constexpr int STAGEB = NT * TILEB;
    static constexpr int AH = 0;
    static constexpr int AL = (PASSES == 3) ? TILEB : 0;
    static constexpr int BH = (PASSES == 3) ? 2 * TILEB : TILEB;
    static constexpr int BL = (PASSES == 2) ? 2 * TILEB : 3 * TILEB;
    static constexpr int SMEM = 3 * STAGEB;
};

// 512 threads: exactly one 16B chunk of A and of B per thread per tile.
template<int PASSES>
__device__ __forceinline__ void issue_tile(
    uint32_t sbase, const char* Ah, const char* Al, const char* Bh, const char* Bl,
    int lda, int ldb, int row0, int col0, int k0, int tid)
{
    using L = Lay<PASSES>;
    const int r = tid >> 2, ch = tid & 3;
    const uint32_t so = (uint32_t)(r * (SROW * 2) + ch * 16);
    const size_t gA = ((size_t)(row0 + r) * lda + k0 + ch * 8) * 2;
    const size_t gB = ((size_t)(col0 + r) * ldb + k0 + ch * 8) * 2;
    CP16(sbase + L::AH + so, Ah + gA);
    if (PASSES == 3) CP16(sbase + L::AL + so, Al + gA);
    CP16(sbase + L::BH + so, Bh + gB);
    if (PASSES >= 2) CP16(sbase + L::BL + so, Bl + gB);
}

template<int PASSES>
__global__ void __launch_bounds__(512, 2) gemm_mma(
    const __half* __restrict__ Ahi, const __half* __restrict__ Alo,
    int lda, long long sA,
    const __half* __restrict__ Bhi, const __half* __restrict__ Blo,
    const __half* __restrict__ Bhi2, int ldb, long long sB,
    void* __restrict__ Cout, void* __restrict__ CoutB,
    int ldc, long long sC,
    int K, const float* __restrict__ bias, const float* __restrict__ bias2,
    int biasMode, float cScale, int doRelu, int splitOut, int dual)
{
    using L = Lay<PASSES>;
    extern __shared__ char smem[];
    const uint32_t sb = smem_u32(smem);
    const int tid  = threadIdx.x;
    const int lane = tid & 31;
    const int wid  = tid >> 5;          // 0..15
    const int wm   = wid & 3;           // m: 32*wm
    const int wn   = wid >> 2;          // n: 32*wn
    const int row0 = blockIdx.y * 128;
    const int col0 = blockIdx.x * 128;

    const int z = blockIdx.z;
    const char *Ah, *Al, *Bh, *Bl;
    const float* bvp = bias;
    void *Co = Cout;
    if (dual && z) {
        Ah = (const char*)(Ahi + 512);
        Al = nullptr;
        Bh = (const char*)Bhi2;  Bl = nullptr;
        bvp = bias2;  Co = CoutB;
    } else {
        Ah = (const char*)(Ahi + (long long)z * sA);
        Al = (const char*)(Alo ? Alo + (long long)z * sA : nullptr);
        Bh = (const char*)(Bhi + (long long)z * sB);
        Bl = (const char*)(Blo ? Blo + (long long)z * sB : nullptr);
    }

    float acc[2][4][4];                 // warp 32x32: 2 m16 x 4 n8
#pragma unroll
    for (int mt = 0; mt < 2; mt++)
#pragma unroll
        for (int nt = 0; nt < 4; nt++)
#pragma unroll
            for (int q = 0; q < 4; q++) acc[mt][nt][q] = 0.0f;

    const int frow = (lane & 7) | (((lane >> 3) & 1) << 3);
    const int fkc  = (lane >> 4) * 8;

    const int T = K / 32;   // >= 16 always
    issue_tile<PASSES>(sb + 0 * L::STAGEB, Ah, Al, Bh, Bl, lda, ldb, row0, col0, 0, tid);
    CP_COMMIT();
    issue_tile<PASSES>(sb + 1 * L::STAGEB, Ah, Al, Bh, Bl, lda, ldb, row0, col0, 32, tid);
    CP_COMMIT();

    int sidx = 0;
    for (int t = 0; t < T; ++t) {
        if (t + 1 < T) { CP_WAIT1(); } else { CP_WAIT0(); }
        __syncthreads();

        const uint32_t st = sb + sidx * L::STAGEB;
#pragma unroll
        for (int kh = 0; kh < 2; ++kh) {
            const int kb = kh * 16 + fkc;
            if (PASSES == 1) {
                uint32_t ah[2][4], bh2[2][4];
#pragma unroll
                for (int mt = 0; mt < 2; mt++)
                    ldsm4(ah[mt], st + L::AH +
                          (uint32_t)(((wm * 32 + mt * 16 + frow) * SROW + kb) * 2));
#pragma unroll
                for (int bt = 0; bt < 2; bt++)
                    ldsm4(bh2[bt], st + L::BH +
                          (uint32_t)(((wn * 32 + bt * 16 + frow) * SROW + kb) * 2));
#pragma unroll
                for (int bt = 0; bt < 2; bt++)
#pragma unroll
                    for (int p = 0; p < 2; p++)
#pragma unroll
                        for (int mt = 0; mt < 2; mt++)
                            mma_f16(acc[mt][bt * 2 + p], ah[mt],
                                    bh2[bt][p], bh2[bt][p + 2]);
            } else {
                uint32_t ah[2][4], al[2][4];
#pragma unroll
                for (int mt = 0; mt < 2; mt++) {
                    const uint32_t off =
                        (uint32_t)(((wm * 32 + mt * 16 + frow) * SROW + kb) * 2);
                    ldsm4(ah[mt], st + L::AH + off);
                    if (PASSES == 3) ldsm4(al[mt], st + L::AL + off);
                }
#pragma unroll
                for (int bt = 0; bt < 2; bt++) {
                    uint32_t bh[4], bl[4];
                    const uint32_t off =
                        (uint32_t)(((wn * 32 + bt * 16 + frow) * SROW + kb) * 2);
                    ldsm4(bh, st + L::BH + off);
                    ldsm4(bl, st + L::BL + off);
#pragma unroll
                    for (int mt = 0; mt < 2; mt++)
#pragma unroll
                        for (int p = 0; p < 2; p++)
                            mma_f16(acc[mt][bt * 2 + p], ah[mt], bh[p], bh[p + 2]);
#pragma unroll
                    for (int mt = 0; mt < 2; mt++)
#pragma unroll
                        for (int p = 0; p < 2; p++)
                            mma_f16(acc[mt][bt * 2 + p], ah[mt], bl[p], bl[p + 2]);
                    if (PASSES == 3) {
#pragma unroll
                        for (int mt = 0; mt < 2; mt++)
#pragma unroll
                            for (int p = 0; p < 2; p++)
                                mma_f16(acc[mt][bt * 2 + p], al[mt], bh[p], bh[p + 2]);
                    }
                }
            }
        }

        if (t + 2 < T) {
            int widx = sidx + 2; if (widx >= 3) widx -= 3;
            issue_tile<PASSES>(sb + widx * L::STAGEB, Ah, Al, Bh, Bl,
                               lda, ldb, row0, col0, (t + 2) * 32, tid);
            CP_COMMIT();
        }
        sidx = (sidx + 1 == 3) ? 0 : sidx + 1;
    }

    // ============================ epilogue ============================
    const int cbytes = (splitOut == 0) ? 4 : 2;
    char* Cb = (char*)Co + (dual ? 0 : (size_t)z * sC * cbytes);

#pragma unroll
    for (int mt = 0; mt < 2; mt++) {
        const long long r0 = row0 + wm * 32 + mt * 16 + (lane >> 2);
#pragma unroll
        for (int nt = 0; nt < 4; nt++) {
            const int c0 = col0 + wn * 32 + nt * 8 + (lane & 3) * 2;
            float b0 = 0.0f, b1 = 0.0f;
            if (biasMode == 1)      { b0 = bvp[c0]; b1 = bvp[c0 + 1]; }
            else if (biasMode == 2) { b0 = bvp[0];  b1 = bvp[0]; }

            float v00 = fmaf(acc[mt][nt][0], cScale, b0);
            float v01 = fmaf(acc[mt][nt][1], cScale, b1);
            float v10 = fmaf(acc[mt][nt][2], cScale, b0);
            float v11 = fmaf(acc[mt][nt][3], cScale, b1);
            if (doRelu) {
                v00 = fmaxf(v00, 0.0f); v01 = fmaxf(v01, 0.0f);
                v10 = fmaxf(v10, 0.0f); v11 = fmaxf(v11, 0.0f);
            }

            if (splitOut == 0) {
                *(float2*)(Cb + (r0 * ldc + c0) * 4)       = make_float2(v00, v01);
                *(float2*)(Cb + ((r0 + 8) * ldc + c0) * 4) = make_float2(v10, v11);
            } else {
                __half h00 = __float2half_rn(v00), h01 = __float2half_rn(v01);
                __half h10 = __float2half_rn(v10), h11 = __float2half_rn(v11);
                uint32_t ph0 = (uint32_t)__half_as_ushort(h00) |
                               ((uint32_t)__half_as_ushort(h01) << 16);
                uint32_t ph1 = (uint32_t)__half_as_ushort(h10) |
                               ((uint32_t)__half_as_ushort(h11) << 16);
                *(uint32_t*)(Cb + (r0 * ldc + c0) * 2)       = ph0;
                *(uint32_t*)(Cb + ((r0 + 8) * ldc + c0) * 2) = ph1;
            }
        }
    }
}

// ============================ launch ============================
extern "C" void kernel_launch(void* const* d_in, const int* in_sizes, int n_in,
                              void* d_out, int out_size)
{
    const float* X   = (const float*)d_in[0];
    const float* w1h = (const float*)d_in[1];
    const float* b1h = (const float*)d_in[2];
    const float* w2h = (const float*)d_in[3];
    const float* b2h = (const float*)d_in[4];
    const float* w1d = (const float*)d_in[5];
    const float* b1d = (const float*)d_in[6];
    const float* w2d = (const float*)d_in[7];
    const float* b2d = (const float*)d_in[8];
    const float* Wb  = (const float*)d_in[9];
    const float* bb  = (const float*)d_in[10];
    float* out = (float*)d_out;

    __half* hb = nullptr;
    cudaGetSymbolAddress((void**)&hb, g_h);
    float* vecs = nullptr;
    cudaGetSymbolAddress((void**)&vecs, g_vec);

    __half *Xh    = hb + O_XH;
    __half *W1Ch  = hb + O_W1C_H;
    __half *W2Hh  = hb + O_W2H_H;
    __half *WBh   = hb + O_WB_H,   *WBl   = hb + O_WB_L;
    __half *W2DTh = hb + O_W2DT_H, *W2DTl = hb + O_W2DT_L;
    __half *WPh   = hb + O_WP_H;
    __half *TTh   = hb + O_TT_H;
    __half *HDh   = hb + O_HD_H;
    __half *DWh   = hb + O_DW_H;

    float* b1c   = vecs + 0 * 1024;
    float* b2h_p = vecs + 1 * 1024;
    float* bpr   = vecs + 2 * 1024;

    cudaFuncSetAttribute(gemm_mma<1>, cudaFuncAttributeMaxDynamicSharedMemorySize,
                         Lay<1>::SMEM);
    cudaFuncSetAttribute(gemm_mma<3>, cudaFuncAttributeMaxDynamicSharedMemorySize,
                         Lay<3>::SMEM);

    // launch 0: X -> fp16
    conv_x<<<(unsigned)(EL_X / 4 / 256), 256>>>(X, Xh);
    // launch 1: weight prep (scaled x32) + biases
    prep_weights<<<7686, 256>>>(w1h, w1d, w2h, Wb, w2d, b1h, b1d, b2h, b2d,
                                W1Ch, W2Hh, WBh, WBl, W2DTh, W2DTl,
                                b1c, b2h_p, bpr);

    // launch 2: W' = Wb @ w2d (3-pass, hi-only store of 32*W')
    {
        dim3 g(4, 4, 1);
        gemm_mma<3><<<g, 512, Lay<3>::SMEM>>>(
            WBh, WBl, 512, 0, W2DTh, W2DTl, nullptr, 512, 0,
            WPh, nullptr, 512, 0, 512, nullptr, nullptr, 0, CDESC, 0, 2, 0);
    }
    // launch 3: stage 1: TT = ReLU(X @ W1C^T /32 + b1c), 1-pass, hi out
    {
        dim3 g(8, 64, 1);
        gemm_mma<1><<<g, 512, Lay<1>::SMEM>>>(
            Xh, nullptr, 1024, 0, W1Ch, nullptr, nullptr, 1024, 0,
            TTh, nullptr, 1024, 0, 1024, b1c, nullptr, 1, CDESC, 1, 2, 0);
    }
    // launch 4: stage 2 merged, 1-pass (z=0: head -> hi; z=1: depW -> hi)
    {
        dim3 g(4, 64, 2);
        gemm_mma<1><<<g, 512, Lay<1>::SMEM>>>(
            TTh, nullptr, 1024, 0, W2Hh, nullptr, WPh, 512, 0,
            HDh, DWh, 512, 0, 512, b2h_p, bpr, 1, CDESC, 0, 2, 1);
    }
    // launch 5: final batched, 1-pass: out[b] = head[b] @ depW[b]^T + bb (fp32)
    {
        dim3 g(4, 4, 16);
        const long long sAB = 512LL * 512;
        gemm_mma<1><<<g, 512, Lay<1>::SMEM>>>(
            HDh, nullptr, 512, sAB, DWh, nullptr, nullptr, 512, sAB,
            out, nullptr, 512, sAB, 512, bb, nullptr, 2, 1.0f, 0, 0, 0);
    }
}

// round 17
// speedup vs baseline: 1.0763x; 1.0201x over previous
#include <cuda_runtime.h>
#include <cuda_fp16.h>
#include <cstdint>

// BiaffineAttention  B=16, S=512, H=1024, A=500 (padded to 512)
// GEMMs via mma.sync fp16 (m16n8k16), fp32 accum, 3-stage cp.async pipeline.
// Weights pre-scaled by 32, descaled in epilogue.
//   TT   = ReLU(X @ [w1h;w1d]^T + b1c)   1-pass -> fp16 hi
//   W'   = Wb @ w2d (3-pass, hi store) ; b' = Wb @ b2d
//   head = TT[:, :512] @ w2h^T + b2h     1-pass -> fp16 hi   (z=0)
//   depW = TT[:, 512:] @ W'^T + b'       1-pass -> fp16 hi   (z=1)
//   out[b] = head[b] @ depW[b]^T + bb    1-pass (fp32 out)
// R17: strength-reduced addressing (hoisted 64-bit global pointer math +
//      precomputed ldsm smem offsets). 512 thr / 16 warps, 2 CTAs/SM.

// ============================ PTX helpers ============================
__device__ __forceinline__ uint32_t smem_u32(const void* p) {
    uint32_t a;
    asm("{ .reg .u64 t; cvta.to.shared.u64 t, %1; cvt.u32.u64 %0, t; }"
        : "=r"(a) : "l"(p));
    return a;
}

__device__ __forceinline__ void ldsm4(uint32_t* r, uint32_t addr) {
    asm volatile("ldmatrix.sync.aligned.m8n8.x4.shared.b16 {%0,%1,%2,%3}, [%4];"
        : "=r"(r[0]), "=r"(r[1]), "=r"(r[2]), "=r"(r[3]) : "r"(addr));
}

__device__ __forceinline__ void mma_f16(float* c, const uint32_t* a,
                                        uint32_t b0, uint32_t b1) {
    asm volatile("mma.sync.aligned.m16n8k16.row.col.f32.f16.f16.f32 "
        "{%0,%1,%2,%3}, {%4,%5,%6,%7}, {%8,%9}, {%0,%1,%2,%3};"
        : "+f"(c[0]), "+f"(c[1]), "+f"(c[2]), "+f"(c[3])
        : "r"(a[0]), "r"(a[1]), "r"(a[2]), "r"(a[3]), "r"(b0), "r"(b1));
}

#define CP16(s, g) \
    asm volatile("cp.async.cg.shared.global [%0], [%1], 16;" :: "r"(s), "l"(g))
#define CP_COMMIT() asm volatile("cp.async.commit_group;" ::: "memory")
#define CP_WAIT0()  asm volatile("cp.async.wait_group 0;" ::: "memory")
#define CP_WAIT1()  asm volatile("cp.async.wait_group 1;" ::: "memory")

// ============================ scratch ============================
static constexpr long long EL_X   = 8192LL * 1024;
static constexpr long long EL_W1C = 1024LL * 1024;
static constexpr long long EL_S   = 512LL * 512;
static constexpr long long EL_TT  = 8192LL * 1024;
static constexpr long long EL_ACT = 8192LL * 512;

static constexpr long long O_XH     = 0;
static constexpr long long O_W1C_H  = O_XH + EL_X;
static constexpr long long O_W2H_H  = O_W1C_H + EL_W1C;
static constexpr long long O_WB_H   = O_W2H_H + EL_S;
static constexpr long long O_WB_L   = O_WB_H + EL_S;
static constexpr long long O_W2DT_H = O_WB_L + EL_S;
static constexpr long long O_W2DT_L = O_W2DT_H + EL_S;
static constexpr long long O_WP_H   = O_W2DT_L + EL_S;
static constexpr long long O_TT_H   = O_WP_H + EL_S;
static constexpr long long O_HD_H   = O_TT_H + EL_TT;
static constexpr long long O_DW_H   = O_HD_H + EL_ACT;
static constexpr long long H_TOTAL  = O_DW_H + EL_ACT;

__device__ __align__(1024) __half g_h[H_TOTAL];
__device__ __align__(1024) float g_vec[3 * 1024];   // b1c[1024], b2h_p[512], bpr[512]

// ============================ prep kernels ============================
__device__ __forceinline__ void split_h(__half* hi, __half* lo, long long i, float v)
{
    __half h = __float2half_rn(v);
    hi[i] = h;
    lo[i] = __float2half_rn(v - __half2float(h));
}

__global__ void conv_x(const float* __restrict__ X, __half* __restrict__ Xh)
{
    long long idx = ((long long)blockIdx.x * blockDim.x + threadIdx.x) * 4;
    float4 v = *(const float4*)(X + idx);
    __half h[4] = {__float2half_rn(v.x), __float2half_rn(v.y),
                   __float2half_rn(v.z), __float2half_rn(v.w)};
    *(uint2*)(Xh + idx) = *(uint2*)h;
}

#define WSCALE 32.0f
#define CDESC  0.03125f

__global__ void prep_weights(
    const float* __restrict__ w1h, const float* __restrict__ w1d,
    const float* __restrict__ w2h, const float* __restrict__ Wb,
    const float* __restrict__ w2d,
    const float* __restrict__ b1h, const float* __restrict__ b1d,
    const float* __restrict__ b2h, const float* __restrict__ b2d,
    __half* __restrict__ W1Ch,
    __half* __restrict__ W2Hh,
    __half* __restrict__ WBh,  __half* __restrict__ WBl,
    __half* __restrict__ W2DTh,__half* __restrict__ W2DTl,
    float* __restrict__ b1c, float* __restrict__ b2h_p, float* __restrict__ bpr)
{
    const int bx = blockIdx.x;
    const int tid = threadIdx.x;

    if (bx < 4096) {
        const int half_ = bx >> 11;
        const long long e = ((long long)(bx & 2047)) * 256 + tid;
        const int r = (int)(e >> 10);
        const float* src = half_ ? w1d : w1h;
        float v = (r < 500) ? WSCALE * src[(long long)r * 1024 + (e & 1023)] : 0.0f;
        W1Ch[(long long)half_ * 512 * 1024 + e] = __float2half_rn(v);
    } else if (bx < 7168) {
        const int sec = (bx - 4096) >> 10;
        const long long e = ((long long)((bx - 4096) & 1023)) * 256 + tid;
        const int r = (int)(e >> 9), c = (int)(e & 511);
        float v = 0.0f;
        if (sec == 0) {
            if (r < 500 && c < 500) v = WSCALE * w2h[r * 500 + c];
            W2Hh[e] = __float2half_rn(v);
        } else if (sec == 1) {
            if (r < 500 && c < 500) v = WSCALE * Wb[r * 500 + c];
            split_h(WBh, WBl, e, v);
        } else {
            if (r < 500 && c < 500) v = WSCALE * w2d[c * 500 + r];
            split_h(W2DTh, W2DTl, e, v);
        }
    } else if (bx < 7680) {
        const int j = bx - 7168;
        __shared__ float red[8];
        float s = 0.0f;
        if (j < 500)
            for (int a = tid; a < 500; a += 256) s += Wb[j * 500 + a] * b2d[a];
#pragma unroll
        for (int o = 16; o > 0; o >>= 1) s += __shfl_down_sync(0xffffffffu, s, o);
        if ((tid & 31) == 0) red[tid >> 5] = s;
        __syncthreads();
        if (tid == 0) {
            float t = 0.0f;
#pragma unroll
            for (int q = 0; q < 8; q++) t += red[q];
            bpr[j] = (j < 500) ? t : 0.0f;
        }
    } else {
        const int e = (bx - 7680) * 256 + tid;
        if (e < 1024) {
            const int c = e & 511;
            b1c[e] = (c < 500) ? ((e < 512) ? b1h[c] : b1d[c]) : 0.0f;
        } else if (e < 1536) {
            const int c = e - 1024;
            b2h_p[c] = (c < 500) ? b2h[c] : 0.0f;
        }
    }
}

// ============================ main GEMM ============================
// C[M,N] = A[M,K] @ B[N,K]^T.
// PASSES=1: Ahi@Bhi.  PASSES=3: + Ahi@Blo + Alo@Bhi.
// CTA 128x128, 512 threads = 16 warps (4M x 4N), warp tile 32x32, BK=32,
// 3-stage cp.async ring, one __syncthreads per k-iter, 2 CTAs/SM.
// splitOut: 0=fp32, 2=fp16 hi only. dual: z picks operand set.
#define SROW 40
#define TILEB (128 * SROW * 2)   // 10240 B per matrix tile
#define MT_STRIDE (16 * SROW * 2)  // 1280 B between m16 fragments

template<int PASSES>
struct Lay {
    static constexpr int NT = (PASSES == 1) ? 2 : (PASSES == 2) ? 3 : 4;
    static constexpr int STAGEB = NT * TILEB;
    static constexpr int AH = 0;
    static constexpr int AL = (PASSES == 3) ? TILEB : 0;
    static constexpr int BH = (PASSES == 3) ? 2 * TILEB : TILEB;
    static constexpr int BL = (PASSES == 2) ? 2 * TILEB : 3 * TILEB;
    static constexpr int SMEM = 3 * STAGEB;
};

// Strength-reduced issue: global pointers precomputed per thread, k offset
// is a single 32-bit byte offset (k0*2).
template<int PASSES>
__device__ __forceinline__ void issue_tile(
    uint32_t sbase, uint32_t so,
    const char* aG, const char* alG, const char* bG, const char* blG,
    uint32_t k2)
{
    using L = Lay<PASSES>;
    CP16(sbase + L::AH + so, aG + k2);
    if (PASSES == 3) CP16(sbase + L::AL + so, alG + k2);
    CP16(sbase + L::BH + so, bG + k2);
    if (PASSES >= 2) CP16(sbase + L::BL + so, blG + k2);
}

template<int PASSES>
__global__ void __launch_bounds__(512, 2) gemm_mma(
    const __half* __restrict__ Ahi, const __half* __restrict__ Alo,
    int lda, long long sA,
    const __half* __restrict__ Bhi, const __half* __restrict__ Blo,
    const __half* __restrict__ Bhi2, int ldb, long long sB,
    void* __restrict__ Cout, void* __restrict__ CoutB,
    int ldc, long long sC,
    int K, const float* __restrict__ bias, const float* __restrict__ bias2,
    int biasMode, float cScale, int doRelu, int splitOut, int dual)
{
    using L = Lay<PASSES>;
    extern __shared__ char smem[];
    const uint32_t sb = smem_u32(smem);
    const int tid  = threadIdx.x;
    const int lane = tid & 31;
    const int wid  = tid >> 5;          // 0..15
    const int wm   = wid & 3;           // m: 32*wm
    const int wn   = wid >> 2;          // n: 32*wn
    const int row0 = blockIdx.y * 128;
    const int col0 = blockIdx.x * 128;

    const int z = blockIdx.z;
    const __half *Ah_, *Al_, *Bh_, *Bl_;
    const float* bvp = bias;
    void *Co = Cout;
    if (dual && z) {
        Ah_ = Ahi + 512;  Al_ = nullptr;
        Bh_ = Bhi2;       Bl_ = nullptr;
        bvp = bias2;  Co = CoutB;
    } else {
        Ah_ = Ahi + (long long)z * sA;
        Al_ = Alo ? Alo + (long long)z * sA : nullptr;
        Bh_ = Bhi + (long long)z * sB;
        Bl_ = Blo ? Blo + (long long)z * sB : nullptr;
    }

    // ---- hoisted load addressing (64-bit math ONCE) ----
    const int lr = tid >> 2, lch = tid & 3;
    const uint32_t so = (uint32_t)(lr * (SROW * 2) + lch * 16);
    const size_t aRow = ((size_t)(row0 + lr) * lda + lch * 8) * 2;
    const size_t bRow = ((size_t)(col0 + lr) * ldb + lch * 8) * 2;
    const char* aG  = (const char*)Ah_ + aRow;
    const char* bG  = (const char*)Bh_ + bRow;
    const char* alG = (PASSES == 3) ? (const char*)Al_ + aRow : nullptr;
    const char* blG = (PASSES >= 2) ? (const char*)Bl_ + bRow : nullptr;

    // ---- hoisted ldsm smem offsets ----
    const int frow = (lane & 7) | (((lane >> 3) & 1) << 3);
    const int fkc  = (lane >> 4) * 8;
    const uint32_t aOff = (uint32_t)(((wm * 32 + frow) * SROW + fkc) * 2);
    const uint32_t bOff = (uint32_t)(((wn * 32 + frow) * SROW + fkc) * 2);

    float acc[2][4][4];                 // warp 32x32: 2 m16 x 4 n8
#pragma unroll
    for (int mt = 0; mt < 2; mt++)
#pragma unroll
        for (int nt = 0; nt < 4; nt++)
#pragma unroll
            for (int q = 0; q < 4; q++) acc[mt][nt][q] = 0.0f;

    const int T = K / 32;   // >= 16 always
    issue_tile<PASSES>(sb + 0 * L::STAGEB, so, aG, alG, bG, blG, 0u);
    CP_COMMIT();
    issue_tile<PASSES>(sb + 1 * L::STAGEB, so, aG, alG, bG, blG, 64u);
    CP_COMMIT();

    int sidx = 0;
    for (int t = 0; t < T; ++t) {
        if (t + 1 < T) { CP_WAIT1(); } else { CP_WAIT0(); }
        __syncthreads();

        const uint32_t stA = sb + sidx * L::STAGEB + L::AH + aOff;
        const uint32_t stB = sb + sidx * L::STAGEB + L::BH + bOff;
#pragma unroll
        for (int kh = 0; kh < 2; ++kh) {
            const uint32_t ka = (uint32_t)(kh * 32);
            if (PASSES == 1) {
                uint32_t ah[2][4], bh2[2][4];
                ldsm4(ah[0],  stA + ka);
                ldsm4(ah[1],  stA + MT_STRIDE + ka);
                ldsm4(bh2[0], stB + ka);
                ldsm4(bh2[1], stB + MT_STRIDE + ka);
#pragma unroll
                for (int bt = 0; bt < 2; bt++)
#pragma unroll
                    for (int p = 0; p < 2; p++)
#pragma unroll
                        for (int mt = 0; mt < 2; mt++)
                            mma_f16(acc[mt][bt * 2 + p], ah[mt],
                                    bh2[bt][p], bh2[bt][p + 2]);
            } else {
                const uint32_t stAl = sb + sidx * L::STAGEB + L::AL + aOff;
                const uint32_t stBl = sb + sidx * L::STAGEB + L::BL + bOff;
                uint32_t ah[2][4], al[2][4];
#pragma unroll
                for (int mt = 0; mt < 2; mt++) {
                    ldsm4(ah[mt], stA + mt * MT_STRIDE + ka);
                    if (PASSES == 3) ldsm4(al[mt], stAl + mt * MT_STRIDE + ka);
                }
#pragma unroll
                for (int bt = 0; bt < 2; bt++) {
                    uint32_t bh[4], bl[4];
                    ldsm4(bh, stB + bt * MT_STRIDE + ka);
                    ldsm4(bl, stBl + bt * MT_STRIDE + ka);
#pragma unroll
                    for (int mt = 0; mt < 2; mt++)
#pragma unroll
                        for (int p = 0; p < 2; p++)
                            mma_f16(acc[mt][bt * 2 + p], ah[mt], bh[p], bh[p + 2]);
#pragma unroll
                    for (int mt = 0; mt < 2; mt++)
#pragma unroll
                        for (int p = 0; p < 2; p++)
                            mma_f16(acc[mt][bt * 2 + p], ah[mt], bl[p], bl[p + 2]);
                    if (PASSES == 3) {
#pragma unroll
                        for (int mt = 0; mt < 2; mt++)
#pragma unroll
                            for (int p = 0; p < 2; p++)
                                mma_f16(acc[mt][bt * 2 + p], al[mt], bh[p], bh[p + 2]);
                    }
                }
            }
        }

        if (t + 2 < T) {
            int widx = sidx + 2; if (widx >= 3) widx -= 3;
            issue_tile<PASSES>(sb + widx * L::STAGEB, so, aG, alG, bG, blG,
                               (uint32_t)((t + 2) << 6));
            CP_COMMIT();
        }
        sidx = (sidx + 1 == 3) ? 0 : sidx + 1;
    }

    // ============================ epilogue ============================
    const int cbytes = (splitOut == 0) ? 4 : 2;
    char* Cb = (char*)Co + (dual ? 0 : (size_t)z * sC * cbytes);

#pragma unroll
    for (int mt = 0; mt < 2; mt++) {
        const long long r0 = row0 + wm * 32 + mt * 16 + (lane >> 2);
#pragma unroll
        for (int nt = 0; nt < 4; nt++) {
            const int c0 = col0 + wn * 32 + nt * 8 + (lane & 3) * 2;
            float b0 = 0.0f, b1 = 0.0f;
            if (biasMode == 1)      { b0 = bvp[c0]; b1 = bvp[c0 + 1]; }
            else if (biasMode == 2) { b0 = bvp[0];  b1 = bvp[0]; }

            float v00 = fmaf(acc[mt][nt][0], cScale, b0);
            float v01 = fmaf(acc[mt][nt][1], cScale, b1);
            float v10 = fmaf(acc[mt][nt][2], cScale, b0);
            float v11 = fmaf(acc[mt][nt][3], cScale, b1);
            if (doRelu) {
                v00 = fmaxf(v00, 0.0f); v01 = fmaxf(v01, 0.0f);
                v10 = fmaxf(v10, 0.0f); v11 = fmaxf(v11, 0.0f);
            }

            if (splitOut == 0) {
                *(float2*)(Cb + (r0 * ldc + c0) * 4)       = make_float2(v00, v01);
                *(float2*)(Cb + ((r0 + 8) * ldc + c0) * 4) = make_float2(v10, v11);
            } else {
                __half h00 = __float2half_rn(v00), h01 = __float2half_rn(v01);
                __half h10 = __float2half_rn(v10), h11 = __float2half_rn(v11);
                uint32_t ph0 = (uint32_t)__half_as_ushort(h00) |
                               ((uint32_t)__half_as_ushort(h01) << 16);
                uint32_t ph1 = (uint32_t)__half_as_ushort(h10) |
                               ((uint32_t)__half_as_ushort(h11) << 16);
                *(uint32_t*)(Cb + (r0 * ldc + c0) * 2)       = ph0;
                *(uint32_t*)(Cb + ((r0 + 8) * ldc + c0) * 2) = ph1;
            }
        }
    }
}

// ============================ launch ============================
extern "C" void kernel_launch(void* const* d_in, const int* in_sizes, int n_in,
                              void* d_out, int out_size)
{
    const float* X   = (const float*)d_in[0];
    const float* w1h = (const float*)d_in[1];
    const float* b1h = (const float*)d_in[2];
    const float* w2h = (const float*)d_in[3];
    const float* b2h = (const float*)d_in[4];
    const float* w1d = (const float*)d_in[5];
    const float* b1d = (const float*)d_in[6];
    const float* w2d = (const float*)d_in[7];
    const float* b2d = (const float*)d_in[8];
    const float* Wb  = (const float*)d_in[9];
    const float* bb  = (const float*)d_in[10];
    float* out = (float*)d_out;

    __half* hb = nullptr;
    cudaGetSymbolAddress((void**)&hb, g_h);
    float* vecs = nullptr;
    cudaGetSymbolAddress((void**)&vecs, g_vec);

    __half *Xh    = hb + O_XH;
    __half *W1Ch  = hb + O_W1C_H;
    __half *W2Hh  = hb + O_W2H_H;
    __half *WBh   = hb + O_WB_H,   *WBl   = hb + O_WB_L;
    __half *W2DTh = hb + O_W2DT_H, *W2DTl = hb + O_W2DT_L;
    __half *WPh   = hb + O_WP_H;
    __half *TTh   = hb + O_TT_H;
    __half *HDh   = hb + O_HD_H;
    __half *DWh   = hb + O_DW_H;

    float* b1c   = vecs + 0 * 1024;
    float* b2h_p = vecs + 1 * 1024;
    float* bpr   = vecs + 2 * 1024;

    cudaFuncSetAttribute(gemm_mma<1>, cudaFuncAttributeMaxDynamicSharedMemorySize,
                         Lay<1>::SMEM);
    cudaFuncSetAttribute(gemm_mma<3>, cudaFuncAttributeMaxDynamicSharedMemorySize,
                         Lay<3>::SMEM);

    // launch 0: X -> fp16
    conv_x<<<(unsigned)(EL_X / 4 / 256), 256>>>(X, Xh);
    // launch 1: weight prep (scaled x32) + biases
    prep_weights<<<7686, 256>>>(w1h, w1d, w2h, Wb, w2d, b1h, b1d, b2h, b2d,
                                W1Ch, W2Hh, WBh, WBl, W2DTh, W2DTl,
                                b1c, b2h_p, bpr);

    // launch 2: W' = Wb @ w2d (3-pass, hi-only store of 32*W')
    {
        dim3 g(4, 4, 1);
        gemm_mma<3><<<g, 512, Lay<3>::SMEM>>>(
            WBh, WBl, 512, 0, W2DTh, W2DTl, nullptr, 512, 0,
            WPh, nullptr, 512, 0, 512, nullptr, nullptr, 0, CDESC, 0, 2, 0);
    }
    // launch 3: stage 1: TT = ReLU(X @ W1C^T /32 + b1c), 1-pass, hi out
    {
        dim3 g(8, 64, 1);
        gemm_mma<1><<<g, 512, Lay<1>::SMEM>>>(
            Xh, nullptr, 1024, 0, W1Ch, nullptr, nullptr, 1024, 0,
            TTh, nullptr, 1024, 0, 1024, b1c, nullptr, 1, CDESC, 1, 2, 0);
    }
    // launch 4: stage 2 merged, 1-pass (z=0: head -> hi; z=1: depW -> hi)
    {
        dim3 g(4, 64, 2);
        gemm_mma<1><<<g, 512, Lay<1>::SMEM>>>(
            TTh, nullptr, 1024, 0, W2Hh, nullptr, WPh, 512, 0,
            HDh, DWh, 512, 0, 512, b2h_p, bpr, 1, CDESC, 0, 2, 1);
    }
    // launch 5: final batched, 1-pass: out[b] = head[b] @ depW[b]^T + bb (fp32)
    {
        dim3 g(4, 4, 16);
        const long long sAB = 512LL * 512;
        gemm_mma<1><<<g, 512, Lay<1>::SMEM>>>(
            HDh, nullptr, 512, sAB, DWh, nullptr, nullptr, 512, sAB,
            out, nullptr, 512, sAB, 512, bb, nullptr, 2, 1.0f, 0, 0, 0);
    }
}